// round 17
// baseline (speedup 1.0000x reference)
#include <cuda_runtime.h>
#include <cstdint>

// SoftNormalShader: gather vertex normals + barycentric interp + softmax RGB blend.
// N=4,H=512,W=512,K=8 ; V=50000, F=100000.
// Inputs (JAX x64 disabled => int arrays are int32):
//   0: verts_normals (V,3) f32   1: bary (P,8,3) f32   2: dists (P,8) f32
//   3: zbuf (P,8) f32            4: faces (F,3) i32    5: pix_to_face (P,8) i32
// Output: (N,H,W,4) float32
//
// R17 = R15 (champion: MUFU-reduced math, 2 px/thread, lb(256,5)) + EARLY L1
// PREFETCH of the gather lines: the first passing sample's face index is known
// right after the cheap z-pass, so its g_fn + bary cache lines are prefetched
// (register-free) BEFORE the 8-exp alpha pass; the loop's __ldg then hits L1.
//   - alpha product via exp(sum x)/prod(1+e^x): 8 RCP -> 1 exp + 1 RCP
//   - sigmoid RCP only for passing samples (~1.06 of 8, GAMMA=1e-4 underflow)
//   - weight exp skipped when arg==0; delta exp skipped when it flushes < EPS

#define KSAMP 8
#define SIGMA_INV  1e4f
#define GAMMA_INV  1e4f
#define ZFAR_F     100.0f
#define INV_RANGE  (1.0f / 99.0f)
#define EPS_F      1e-10f

#define MAXF 131072

__device__ float4 g_fn[MAXF][3];   // per-face packed vertex normals

__global__ __launch_bounds__(256)
void prep_face_normals_kernel(const float* __restrict__ vn,
                              const int*   __restrict__ faces, int F)
{
    int idx = blockIdx.x * blockDim.x + threadIdx.x;   // (face, vert) pairs
    int f = idx / 3;
    int j = idx - f * 3;
    if (f >= F || f >= MAXF) return;
    int v = __ldg(faces + (long long)f * 3 + j);
    const float* n = vn + (long long)v * 3;
    g_fn[f][j] = make_float4(__ldg(n + 0), __ldg(n + 1), __ldg(n + 2), 0.0f);
}

__device__ __forceinline__ void prefetch_l1(const void* p) {
    asm volatile("prefetch.global.L1 [%0];" :: "l"(p));
}

// 7-select binary tree for the prefetch face index (used once per pixel).
__device__ __forceinline__ int sel8i(const int* v, int k) {
    int x01 = (k & 1) ? v[1] : v[0];
    int x23 = (k & 1) ? v[3] : v[2];
    int x45 = (k & 1) ? v[5] : v[4];
    int x67 = (k & 1) ? v[7] : v[6];
    int y0  = (k & 2) ? x23 : x01;
    int y1  = (k & 2) ? x67 : x45;
    return (k & 4) ? y1 : y0;
}

#define PIX_PER_THREAD 2

__global__ __launch_bounds__(256, 5)
void soft_normal_shader_kernel(
    const float* __restrict__ bary,    // (P,8,3)
    const float* __restrict__ dists,   // (P,8)
    const float* __restrict__ zbuf,    // (P,8)
    const int*   __restrict__ p2f,     // (P,8)
    float4*      __restrict__ out,     // (P,) rgba
    int npix)
{
    int tid = blockIdx.x * blockDim.x + threadIdx.x;
    int nthreads = gridDim.x * blockDim.x;

    float4 dv[PIX_PER_THREAD][2], zv[PIX_PER_THREAD][2];
    int4   pv[PIX_PER_THREAD][2];

    // ---- front-batched streaming loads for both pixels (12 x 16B in flight) ----
    #pragma unroll
    for (int j = 0; j < PIX_PER_THREAD; j++) {
        int pix = tid + j * nthreads;
        if (pix >= npix) pix = npix - 1;           // safe clamp (grid is exact anyway)
        const long long base = (long long)pix * KSAMP;
        const float4* dp = reinterpret_cast<const float4*>(dists + base);
        const float4* zp = reinterpret_cast<const float4*>(zbuf  + base);
        const int4*   pp = reinterpret_cast<const int4*>(p2f + base);
        dv[j][0] = __ldcs(dp + 0); dv[j][1] = __ldcs(dp + 1);
        zv[j][0] = __ldcs(zp + 0); zv[j][1] = __ldcs(zp + 1);
        pv[j][0] = __ldcs(pp + 0); pv[j][1] = __ldcs(pp + 1);
    }

    #pragma unroll
    for (int j = 0; j < PIX_PER_THREAD; j++) {
        int pix = tid + j * nthreads;
        if (pix >= npix) continue;
        const long long base = (long long)pix * KSAMP;

        // statically-indexed register views
        float df[KSAMP] = { dv[j][0].x, dv[j][0].y, dv[j][0].z, dv[j][0].w,
                            dv[j][1].x, dv[j][1].y, dv[j][1].z, dv[j][1].w };
        float zf[KSAMP] = { zv[j][0].x, zv[j][0].y, zv[j][0].z, zv[j][0].w,
                            zv[j][1].x, zv[j][1].y, zv[j][1].z, zv[j][1].w };
        int   pf[KSAMP] = { pv[j][0].x, pv[j][0].y, pv[j][0].z, pv[j][0].w,
                            pv[j][1].x, pv[j][1].y, pv[j][1].z, pv[j][1].w };

        // ---- pass A (cheap, no MUFU): z_inv, zmax ----
        float zi[KSAMP];
        float zmax = 0.0f;                 // z_inv >= 0 (masked entries are 0)
        #pragma unroll
        for (int k = 0; k < KSAMP; k++) {
            zi[k] = (pf[k] >= 0) ? (ZFAR_F - zf[k]) * INV_RANGE : 0.0f;
            zmax = fmaxf(zmax, zi[k]);
        }

        // ---- candidate mask: exp((z-zmax)*1e4) flushes to 0 below ~-88 ----
        unsigned mask = 0;
        #pragma unroll
        for (int k = 0; k < KSAMP; k++) {
            if (pf[k] >= 0 && (zi[k] - zmax) * GAMMA_INV > -88.0f)
                mask |= (1u << k);
        }

        // ---- early register-free prefetch of the first passing sample's lines ----
        if (mask) {
            int k0 = __ffs(mask) - 1;
            int f0 = sel8i(pf, k0);
            const char* gp = reinterpret_cast<const char*>(&g_fn[f0][0]);
            prefetch_l1(gp);               // 48B may span 2 x 128B lines
            prefetch_l1(gp + 47);
            prefetch_l1(bary + (base + k0) * 3);
        }

        // ---- pass B (MUFU): alpha product terms; overlaps the prefetch ----
        // (1 - sigmoid(-x)) = e^x/(1+e^x)  =>  prod = exp(sum x)/prod(1+e^x)
        float ex[KSAMP];
        float xsum = 0.0f, qprod = 1.0f;
        #pragma unroll
        for (int k = 0; k < KSAMP; k++) {
            bool valid = pf[k] >= 0;
            float x = df[k] * SIGMA_INV;
            float e = __expf(x);
            ex[k] = e;
            xsum  += valid ? x : 0.0f;
            qprod *= valid ? (1.0f + e) : 1.0f;
        }
        float one_minus_prod = __expf(xsum) / qprod;   // 1 exp + 1 rcp

        // ---- compacted weight + gather loop (~1.06 iterations; L1 hits) ----
        float wsum = 0.0f;
        float accr = 0.0f, accg = 0.0f, accb = 0.0f;
        while (mask) {
            int k = __ffs(mask) - 1;
            mask &= mask - 1;
            float e2 = (zi[k] - zmax) * GAMMA_INV;
            float wm = 1.0f;                 // expf(0)==1 exactly (zmax sample)
            if (e2 != 0.0f) wm = __expf(e2); // rare extra samples only
            float p = 1.0f / (1.0f + ex[k]); // sigmoid RCP only where needed
            float w = p * wm;
            wsum += w;
            // lazy bary: b0,b1 loaded; b2 reconstructed (sum == 1)
            const float* bp = bary + (base + k) * 3;
            float b0 = __ldg(bp + 0);
            float b1 = __ldg(bp + 1);
            float b2 = 1.0f - b0 - b1;
            // single-hop gather: per-face packed normals (prefetched into L1)
            const float4* fn = g_fn[pf[k]];
            float4 n0 = __ldg(fn + 0);
            float4 n1 = __ldg(fn + 1);
            float4 n2 = __ldg(fn + 2);
            accr += w * (b0 * n0.x + b1 * n1.x + b2 * n2.x);
            accg += w * (b0 * n0.y + b1 * n1.y + b2 * n2.y);
            accb += w * (b0 * n0.z + b1 * n1.z + b2 * n2.z);
        }

        // ---- blend; delta exp skipped when it provably flushes under EPS ----
        float darg = (EPS_F - zmax) * GAMMA_INV;
        float delta = EPS_F;
        if (darg > -88.0f)                   // ~never taken (zmax ~ 0.9)
            delta = fmaxf(__expf(darg), EPS_F);
        float inv_denom = 1.0f / (wsum + delta);
        float4 o;
        o.x = (accr + delta) * inv_denom;   // background = (1,1,1)
        o.y = (accg + delta) * inv_denom;
        o.z = (accb + delta) * inv_denom;
        o.w = 1.0f - one_minus_prod;        // 1 - alpha
        __stcs(out + pix, o);
    }
}

extern "C" void kernel_launch(void* const* d_in, const int* in_sizes, int n_in,
                              void* d_out, int out_size)
{
    const float* vn    = (const float*)d_in[0];
    const float* bary  = (const float*)d_in[1];
    const float* dists = (const float*)d_in[2];
    const float* zbuf  = (const float*)d_in[3];
    const int*   faces = (const int*)d_in[4];
    const int*   p2f   = (const int*)d_in[5];
    float4*      out   = (float4*)d_out;

    int F = in_sizes[4] / 3;
    int npix = in_sizes[2] / KSAMP;   // N*H*W

    prep_face_normals_kernel<<<(3 * F + 255) / 256, 256>>>(vn, faces, F);

    int threads = 256;
    int total_threads = (npix + PIX_PER_THREAD - 1) / PIX_PER_THREAD;
    int blocks = (total_threads + threads - 1) / threads;
    soft_normal_shader_kernel<<<blocks, threads>>>(bary, dists, zbuf, p2f, out, npix);
}